// round 2
// baseline (speedup 1.0000x reference)
#include <cuda_runtime.h>
#include <cstdint>

// ---------------------------------------------------------------------------
// LSTM cell fused kernel, sm_103 BASE target (no tcgen05/TMEM available —
// harness PTX target is sm_103, not sm_103a). Ampere-style pipeline:
// cp.async -> SW128-swizzled smem -> ldmatrix -> mma.sync tf32 -> fused epilogue.
//
// gates[B,3H] = [x|h] @ [Wx|Wh]^T ; new_c = sig(gf)*c + sig(gi)*tanh(gg)
// ---------------------------------------------------------------------------

static constexpr int BATCH = 16384;
static constexpr int HID   = 1024;
static constexpr int BM    = 128;   // M rows per CTA
static constexpr int BN_G  = 64;    // N cols per gate per CTA
static constexpr int GATES = 3;
static constexpr int BK    = 32;    // K per stage
static constexpr int KSTEPS = 2048 / BK;   // 64
static constexpr int NSTAGE = 4;

static constexpr uint32_t A_ST  = BM * 128;            // 16 KB
static constexpr uint32_t B_ST  = GATES * BN_G * 128;  // 24 KB
static constexpr uint32_t STAGE = A_ST + B_ST;         // 40 KB
static constexpr uint32_t SMEM_BYTES = 2048 + NSTAGE * STAGE + 1024;

__device__ __forceinline__ uint32_t smem_u32(const void* p) {
    uint32_t a;
    asm("{ .reg .u64 t; cvta.to.shared.u64 t, %1; cvt.u32.u64 %0, t; }"
        : "=r"(a) : "l"(p));
    return a;
}

#define CP_ASYNC16(dst, src) \
    asm volatile("cp.async.cg.shared.global [%0], [%1], 16;" :: "r"(dst), "l"(src) : "memory")
#define CP_COMMIT() asm volatile("cp.async.commit_group;" ::: "memory")

#define LDSM4(r, addr)                                                         \
    asm volatile("ldmatrix.sync.aligned.m8n8.x4.shared.b16 {%0,%1,%2,%3}, [%4];" \
        : "=r"((r)[0]), "=r"((r)[1]), "=r"((r)[2]), "=r"((r)[3]) : "r"(addr))

#define MMA_TF32(d, a, b0, b1)                                                 \
    asm volatile("mma.sync.aligned.m16n8k8.row.col.f32.tf32.tf32.f32 "         \
        "{%0,%1,%2,%3},{%4,%5,%6,%7},{%8,%9},{%0,%1,%2,%3};"                   \
        : "+f"((d)[0]), "+f"((d)[1]), "+f"((d)[2]), "+f"((d)[3])               \
        : "r"((a)[0]), "r"((a)[1]), "r"((a)[2]), "r"((a)[3]), "r"(b0), "r"(b1))

__device__ __forceinline__ uint32_t f2tf(uint32_t v) {
    uint32_t o;
    asm("cvt.rna.tf32.f32 %0, %1;" : "=r"(o) : "r"(v));
    return o;
}

__device__ __forceinline__ float lstm_elem(float gi, float gf, float gg,
                                           float bi, float bf, float bg, float cv) {
    float vi = gi + bi;
    float vf = gf + bf;
    float vg = gg + bg;
    float si = 1.0f / (1.0f + __expf(-vi));
    float sf = 1.0f / (1.0f + __expf(-vf));
    float vgc = fminf(15.0f, fmaxf(-15.0f, vg));
    float e2  = __expf(2.0f * vgc);
    float tg  = (e2 - 1.0f) / (e2 + 1.0f);
    return fmaf(sf, cv, si * tg);
}

__global__ __launch_bounds__(256, 1)
void lstm_mma_kernel(const float* __restrict__ x,  const float* __restrict__ h,
                     const float* __restrict__ c,
                     const float* __restrict__ Wii, const float* __restrict__ Whi,
                     const float* __restrict__ Wif, const float* __restrict__ Whf,
                     const float* __restrict__ Wig, const float* __restrict__ Whg,
                     const float* __restrict__ bii, const float* __restrict__ bhi,
                     const float* __restrict__ bif, const float* __restrict__ bhf,
                     const float* __restrict__ big, const float* __restrict__ bhg,
                     float* __restrict__ out) {
    extern __shared__ char smem_raw[];
    const uint32_t raw   = smem_u32(smem_raw);
    const uint32_t tiles = (raw + 1023u) & ~1023u;                // stage buffers
    float* bias = (float*)(smem_raw + (tiles - raw) + NSTAGE * STAGE); // 192 floats

    const int tid  = threadIdx.x;
    const int lane = tid & 31;
    const int wid  = tid >> 5;
    const int wm   = wid >> 2;      // 0..1  (M half: 64 rows)
    const int wn   = wid & 3;       // 0..3  (16 cols per gate)

    const int m0 = (int)(blockIdx.x >> 4) * BM;
    const int n0 = (int)(blockIdx.x & 15) * BN_G;

    // ---- biases folded: b_x + b_h, per gate, for this n-block -------------
    if (tid < 192) {
        const int g = tid >> 6, j = tid & 63, n = n0 + j;
        float v;
        if (g == 0)      v = bii[n] + bhi[n];
        else if (g == 1) v = bif[n] + bhf[n];
        else             v = big[n] + bhg[n];
        bias[tid] = v;
    }

    // ---- producer per-thread invariants (cp.async) ------------------------
    uint32_t aoffs[4]; long agoff[4];
    #pragma unroll
    for (int i = 0; i < 4; ++i) {
        const int id = tid + i * 256;
        const int row = id >> 3, ch = id & 7;
        aoffs[i] = (uint32_t)(row * 128 + ((ch ^ (row & 7)) << 4));
        agoff[i] = (long)(m0 + row) * HID + ch * 4;
    }
    uint32_t boffs[6]; long bgoff[6]; int bsel[6];
    #pragma unroll
    for (int i = 0; i < 6; ++i) {
        const int id = tid + i * 256;
        const int grow = id >> 3, ch = id & 7;
        const int g = grow >> 6, r = grow & 63;
        boffs[i] = (uint32_t)(grow * 128 + ((ch ^ (r & 7)) << 4));
        bgoff[i] = (long)(n0 + r) * HID + ch * 4;
        bsel[i]  = g;
    }

    // ---- consumer per-lane ldmatrix invariants ----------------------------
    const uint32_t s7 = (uint32_t)(lane & 7);
    const int lmrow = (lane & 7) + ((lane >> 3) & 1) * 8; // row within 16
    const int lkh   = lane >> 4;                          // k-half 0/1
    uint32_t arow[4], brow[3];
    #pragma unroll
    for (int mt = 0; mt < 4; ++mt)
        arow[mt] = (uint32_t)((wm * 64 + mt * 16 + lmrow) * 128);
    #pragma unroll
    for (int g = 0; g < GATES; ++g)
        brow[g] = (uint32_t)((g * 64 + wn * 16 + lmrow) * 128);

    float acc[GATES][4][2][4];
    #pragma unroll
    for (int g = 0; g < GATES; ++g)
        #pragma unroll
        for (int mt = 0; mt < 4; ++mt)
            #pragma unroll
            for (int nt = 0; nt < 2; ++nt)
                #pragma unroll
                for (int q = 0; q < 4; ++q) acc[g][mt][nt][q] = 0.0f;

    // ---- stage loader ------------------------------------------------------
    auto load_stage = [&](int s, int ks) {
        const bool half = ks >= 32;
        const int  kk   = (ks & 31) * BK;
        const float* A  = half ? h : x;
        const float* W0 = half ? Whi : Wii;
        const float* W1 = half ? Whf : Wif;
        const float* W2 = half ? Whg : Wig;
        const uint32_t sAs = tiles + (uint32_t)s * STAGE;
        const uint32_t sBs = sAs + A_ST;
        #pragma unroll
        for (int i = 0; i < 4; ++i)
            CP_ASYNC16(sAs + aoffs[i], A + agoff[i] + kk);
        #pragma unroll
        for (int i = 0; i < 6; ++i) {
            const float* W = (bsel[i] == 0) ? W0 : (bsel[i] == 1) ? W1 : W2;
            CP_ASYNC16(sBs + boffs[i], W + bgoff[i] + kk);
        }
    };

    // ---- pipeline ----------------------------------------------------------
    #pragma unroll
    for (int s = 0; s < NSTAGE - 1; ++s) { load_stage(s, s); CP_COMMIT(); }

    for (int ks = 0; ks < KSTEPS; ++ks) {
        const int pf = ks + NSTAGE - 1;
        if (pf < KSTEPS) load_stage(pf & (NSTAGE - 1), pf);
        CP_COMMIT();
        asm volatile("cp.async.wait_group %0;" :: "n"(NSTAGE - 2));
        __syncthreads();

        const uint32_t sAs = tiles + (uint32_t)(ks & (NSTAGE - 1)) * STAGE;
        const uint32_t sBs = sAs + A_ST;

        #pragma unroll
        for (int kst = 0; kst < 4; ++kst) {
            const uint32_t off = (uint32_t)(((kst * 2 + lkh) ^ s7) << 4);
            uint32_t a[4][4], b[GATES][4];
            #pragma unroll
            for (int mt = 0; mt < 4; ++mt) LDSM4(a[mt], sAs + arow[mt] + off);
            #pragma unroll
            for (int g = 0; g < GATES; ++g) LDSM4(b[g], sBs + brow[g] + off);
            #pragma unroll
            for (int mt = 0; mt < 4; ++mt)
                #pragma unroll
                for (int q = 0; q < 4; ++q) a[mt][q] = f2tf(a[mt][q]);
            #pragma unroll
            for (int g = 0; g < GATES; ++g)
                #pragma unroll
                for (int q = 0; q < 4; ++q) b[g][q] = f2tf(b[g][q]);
            #pragma unroll
            for (int g = 0; g < GATES; ++g)
                #pragma unroll
                for (int mt = 0; mt < 4; ++mt) {
                    MMA_TF32(acc[g][mt][0], a[mt], b[g][0], b[g][2]);
                    MMA_TF32(acc[g][mt][1], a[mt], b[g][1], b[g][3]);
                }
        }
        __syncthreads();
    }

    // ---- epilogue: fully register-resident --------------------------------
    #pragma unroll
    for (int mt = 0; mt < 4; ++mt) {
        const int mrow = m0 + wm * 64 + mt * 16 + (lane >> 2);
        #pragma unroll
        for (int nt = 0; nt < 2; ++nt) {
            const int nl = wn * 16 + nt * 8 + (lane & 3) * 2;
            const float bi0 = bias[nl],       bi1 = bias[nl + 1];
            const float bf0 = bias[64 + nl],  bf1 = bias[64 + nl + 1];
            const float bg0 = bias[128 + nl], bg1 = bias[128 + nl + 1];
            #pragma unroll
            for (int rh = 0; rh < 2; ++rh) {
                const long idx = (long)(mrow + rh * 8) * HID + n0 + nl;
                const float2 cv = *(const float2*)(c + idx);
                float2 ov;
                ov.x = lstm_elem(acc[0][mt][nt][rh * 2],
                                 acc[1][mt][nt][rh * 2],
                                 acc[2][mt][nt][rh * 2], bi0, bf0, bg0, cv.x);
                ov.y = lstm_elem(acc[0][mt][nt][rh * 2 + 1],
                                 acc[1][mt][nt][rh * 2 + 1],
                                 acc[2][mt][nt][rh * 2 + 1], bi1, bf1, bg1, cv.y);
                *(float2*)(out + idx) = ov;
            }
        }
    }
}

extern "C" void kernel_launch(void* const* d_in, const int* in_sizes, int n_in,
                              void* d_out, int out_size) {
    const float* x   = (const float*)d_in[0];
    const float* h   = (const float*)d_in[1];
    const float* c   = (const float*)d_in[2];
    const float* Wii = (const float*)d_in[3];
    const float* bii = (const float*)d_in[4];
    const float* Whi = (const float*)d_in[5];
    const float* bhi = (const float*)d_in[6];
    const float* Wif = (const float*)d_in[7];
    const float* bif = (const float*)d_in[8];
    const float* Whf = (const float*)d_in[9];
    const float* bhf = (const float*)d_in[10];
    const float* Wig = (const float*)d_in[11];
    const float* big = (const float*)d_in[12];
    const float* Whg = (const float*)d_in[13];
    const float* bhg = (const float*)d_in[14];
    float* out = (float*)d_out;

    cudaFuncSetAttribute(lstm_mma_kernel,
                         cudaFuncAttributeMaxDynamicSharedMemorySize, SMEM_BYTES);

    // bid = m_tile*16 + n_block : n fastest -> one wave shares the 24MB W set in L2
    dim3 grid((BATCH / BM) * (HID / BN_G));
    lstm_mma_kernel<<<grid, 256, SMEM_BYTES>>>(
        x, h, c, Wii, Whi, Wif, Whf, Wig, Whg,
        bii, bhi, bif, bhf, big, bhg, out);
}

// round 3
// speedup vs baseline: 1.1747x; 1.1747x over previous
#include <cuda_runtime.h>
#include <cstdint>

// ---------------------------------------------------------------------------
// LSTM cell, sm_103 base target. R3: tf32 rounding hoisted into prepass
// kernels writing __device__ scratch (g_X = [x|h] rounded, g_W = gate-concat
// rounded). Mainloop: cp.async -> swizzled smem -> ldmatrix -> mma.sync tf32
// with NO cvt and single __syncthreads per K-stage. Fused LSTM epilogue.
// ---------------------------------------------------------------------------

static constexpr int BATCH = 16384;
static constexpr int HID   = 1024;
static constexpr int KTOT  = 2048;
static constexpr int BM    = 128;
static constexpr int BN_G  = 64;
static constexpr int GATES = 3;
static constexpr int BK    = 32;
static constexpr int KSTEPS = KTOT / BK;   // 64
static constexpr int NSTAGE = 4;

static constexpr uint32_t A_ST  = BM * 128;            // 16 KB
static constexpr uint32_t B_ST  = GATES * BN_G * 128;  // 24 KB
static constexpr uint32_t STAGE = A_ST + B_ST;         // 40 KB
static constexpr uint32_t SMEM_BYTES = NSTAGE * STAGE + 1024;

// Device scratch: rounded-to-tf32 operands (static allocation is allowed).
__device__ float g_X[(long)BATCH * KTOT];          // 134 MB
__device__ float g_W[(long)GATES * HID * KTOT];    // 25 MB

__device__ __forceinline__ uint32_t smem_u32(const void* p) {
    uint32_t a;
    asm("{ .reg .u64 t; cvta.to.shared.u64 t, %1; cvt.u32.u64 %0, t; }"
        : "=r"(a) : "l"(p));
    return a;
}

#define CP_ASYNC16(dst, src) \
    asm volatile("cp.async.cg.shared.global [%0], [%1], 16;" :: "r"(dst), "l"(src) : "memory")
#define CP_COMMIT() asm volatile("cp.async.commit_group;" ::: "memory")

#define LDSM4(r, addr)                                                         \
    asm volatile("ldmatrix.sync.aligned.m8n8.x4.shared.b16 {%0,%1,%2,%3}, [%4];" \
        : "=r"((r)[0]), "=r"((r)[1]), "=r"((r)[2]), "=r"((r)[3]) : "r"(addr))

#define MMA_TF32(d, a, b0, b1)                                                 \
    asm volatile("mma.sync.aligned.m16n8k8.row.col.f32.tf32.tf32.f32 "         \
        "{%0,%1,%2,%3},{%4,%5,%6,%7},{%8,%9},{%0,%1,%2,%3};"                   \
        : "+f"((d)[0]), "+f"((d)[1]), "+f"((d)[2]), "+f"((d)[3])               \
        : "r"((a)[0]), "r"((a)[1]), "r"((a)[2]), "r"((a)[3]), "r"(b0), "r"(b1))

__device__ __forceinline__ float f2tf_f(float v) {
    uint32_t o;
    asm("cvt.rna.tf32.f32 %0, %1;" : "=r"(o) : "r"(__float_as_uint(v)));
    return __uint_as_float(o);
}

__device__ __forceinline__ float4 round4(float4 v) {
    v.x = f2tf_f(v.x); v.y = f2tf_f(v.y); v.z = f2tf_f(v.z); v.w = f2tf_f(v.w);
    return v;
}

// ---- prepass: round inputs to tf32 and concatenate -------------------------
__global__ __launch_bounds__(256)
void prep_x_kernel(const float* __restrict__ x, const float* __restrict__ h) {
    const long i = (long)blockIdx.x * 256 + threadIdx.x;    // float4 index
    const long row = i >> 9;                                 // 512 f4 per row
    const int  c4  = (int)(i & 511);
    float4 v = (c4 < 256) ? ((const float4*)x)[row * 256 + c4]
                          : ((const float4*)h)[row * 256 + (c4 - 256)];
    ((float4*)g_X)[i] = round4(v);
}

__global__ __launch_bounds__(256)
void prep_w_kernel(const float* __restrict__ Wii, const float* __restrict__ Whi,
                   const float* __restrict__ Wif, const float* __restrict__ Whf,
                   const float* __restrict__ Wig, const float* __restrict__ Whg) {
    const long i = (long)blockIdx.x * 256 + threadIdx.x;    // float4 index
    const long grow = i >> 9;                                // 0..3071
    const int  c4   = (int)(i & 511);
    const int  g    = (int)(grow >> 10);
    const long r    = grow & 1023;
    const float* Wx = (g == 0) ? Wii : (g == 1) ? Wif : Wig;
    const float* Wh = (g == 0) ? Whi : (g == 1) ? Whf : Whg;
    float4 v = (c4 < 256) ? ((const float4*)Wx)[r * 256 + c4]
                          : ((const float4*)Wh)[r * 256 + (c4 - 256)];
    ((float4*)g_W)[i] = round4(v);
}

__device__ __forceinline__ float lstm_elem(float gi, float gf, float gg,
                                           float bi, float bf, float bg, float cv) {
    float vi = gi + bi;
    float vf = gf + bf;
    float vg = gg + bg;
    float si = 1.0f / (1.0f + __expf(-vi));
    float sf = 1.0f / (1.0f + __expf(-vf));
    float vgc = fminf(15.0f, fmaxf(-15.0f, vg));
    float e2  = __expf(2.0f * vgc);
    float tg  = (e2 - 1.0f) / (e2 + 1.0f);
    return fmaf(sf, cv, si * tg);
}

__global__ __launch_bounds__(256, 1)
void lstm_mma_kernel(const float* __restrict__ c,
                     const float* __restrict__ bii, const float* __restrict__ bhi,
                     const float* __restrict__ bif, const float* __restrict__ bhf,
                     const float* __restrict__ big, const float* __restrict__ bhg,
                     float* __restrict__ out) {
    extern __shared__ char smem_raw[];
    const uint32_t raw   = smem_u32(smem_raw);
    const uint32_t tiles = (raw + 1023u) & ~1023u;
    float* bias = (float*)(smem_raw + (tiles - raw) + NSTAGE * STAGE);

    const int tid  = threadIdx.x;
    const int lane = tid & 31;
    const int wid  = tid >> 5;
    const int wm   = wid >> 2;
    const int wn   = wid & 3;

    const int m0 = (int)(blockIdx.x >> 4) * BM;
    const int n0 = (int)(blockIdx.x & 15) * BN_G;

    if (tid < 192) {
        const int g = tid >> 6, j = tid & 63, n = n0 + j;
        float v;
        if (g == 0)      v = bii[n] + bhi[n];
        else if (g == 1) v = bif[n] + bhf[n];
        else             v = big[n] + bhg[n];
        bias[tid] = v;
    }

    // producer invariants --------------------------------------------------
    uint32_t aoffs[4]; const float* asrc[4];
    #pragma unroll
    for (int i = 0; i < 4; ++i) {
        const int id = tid + i * 256;
        const int row = id >> 3, ch = id & 7;
        aoffs[i] = (uint32_t)(row * 128 + ((ch ^ (row & 7)) << 4));
        asrc[i]  = g_X + (long)(m0 + row) * KTOT + ch * 4;
    }
    uint32_t boffs[6]; const float* bsrc[6];
    #pragma unroll
    for (int i = 0; i < 6; ++i) {
        const int id = tid + i * 256;
        const int grow = id >> 3, ch = id & 7;
        const int g = grow >> 6, r = grow & 63;
        boffs[i] = (uint32_t)(grow * 128 + ((ch ^ (r & 7)) << 4));
        bsrc[i]  = g_W + (long)(g * HID + n0 + r) * KTOT + ch * 4;
    }

    // consumer invariants --------------------------------------------------
    const uint32_t s7 = (uint32_t)(lane & 7);
    const int lmrow = (lane & 7) + ((lane >> 3) & 1) * 8;
    const int lkh   = lane >> 4;
    uint32_t arow[4], brow[3];
    #pragma unroll
    for (int mt = 0; mt < 4; ++mt)
        arow[mt] = (uint32_t)((wm * 64 + mt * 16 + lmrow) * 128);
    #pragma unroll
    for (int g = 0; g < GATES; ++g)
        brow[g] = (uint32_t)((g * 64 + wn * 16 + lmrow) * 128);

    float acc[GATES][4][2][4];
    #pragma unroll
    for (int g = 0; g < GATES; ++g)
        #pragma unroll
        for (int mt = 0; mt < 4; ++mt)
            #pragma unroll
            for (int nt = 0; nt < 2; ++nt)
                #pragma unroll
                for (int q = 0; q < 4; ++q) acc[g][mt][nt][q] = 0.0f;

    auto load_stage = [&](int s, int ks) {
        const int kk = ks * BK;
        const uint32_t sAs = tiles + (uint32_t)s * STAGE;
        const uint32_t sBs = sAs + A_ST;
        #pragma unroll
        for (int i = 0; i < 4; ++i)
            CP_ASYNC16(sAs + aoffs[i], asrc[i] + kk);
        #pragma unroll
        for (int i = 0; i < 6; ++i)
            CP_ASYNC16(sBs + boffs[i], bsrc[i] + kk);
    };

    #pragma unroll
    for (int s = 0; s < NSTAGE - 1; ++s) { load_stage(s, s); CP_COMMIT(); }

    for (int ks = 0; ks < KSTEPS; ++ks) {
        asm volatile("cp.async.wait_group %0;" :: "n"(NSTAGE - 2));
        __syncthreads();

        const uint32_t sAs = tiles + (uint32_t)(ks & (NSTAGE - 1)) * STAGE;
        const uint32_t sBs = sAs + A_ST;

        #pragma unroll
        for (int kst = 0; kst < 4; ++kst) {
            const uint32_t off = (uint32_t)(((kst * 2 + lkh) ^ s7) << 4);
            uint32_t a[4][4], b[GATES][4];
            #pragma unroll
            for (int mt = 0; mt < 4; ++mt) LDSM4(a[mt], sAs + arow[mt] + off);
            #pragma unroll
            for (int g = 0; g < GATES; ++g) LDSM4(b[g], sBs + brow[g] + off);
            #pragma unroll
            for (int g = 0; g < GATES; ++g)
                #pragma unroll
                for (int mt = 0; mt < 4; ++mt) {
                    MMA_TF32(acc[g][mt][0], a[mt], b[g][0], b[g][2]);
                    MMA_TF32(acc[g][mt][1], a[mt], b[g][1], b[g][3]);
                }
        }

        // prefetch AFTER compute: single sync per iteration is sufficient
        const int pf = ks + NSTAGE - 1;
        if (pf < KSTEPS) load_stage(pf & (NSTAGE - 1), pf);
        CP_COMMIT();   // empty commits at tail keep the group count uniform
    }

    // epilogue: register-resident -----------------------------------------
    #pragma unroll
    for (int mt = 0; mt < 4; ++mt) {
        const int mrow = m0 + wm * 64 + mt * 16 + (lane >> 2);
        #pragma unroll
        for (int nt = 0; nt < 2; ++nt) {
            const int nl = wn * 16 + nt * 8 + (lane & 3) * 2;
            const float bi0 = bias[nl],       bi1 = bias[nl + 1];
            const float bf0 = bias[64 + nl],  bf1 = bias[64 + nl + 1];
            const float bg0 = bias[128 + nl], bg1 = bias[128 + nl + 1];
            #pragma unroll
            for (int rh = 0; rh < 2; ++rh) {
                const long idx = (long)(mrow + rh * 8) * HID + n0 + nl;
                const float2 cv = *(const float2*)(c + idx);
                float2 ov;
                ov.x = lstm_elem(acc[0][mt][nt][rh * 2],
                                 acc[1][mt][nt][rh * 2],
                                 acc[2][mt][nt][rh * 2], bi0, bf0, bg0, cv.x);
                ov.y = lstm_elem(acc[0][mt][nt][rh * 2 + 1],
                                 acc[1][mt][nt][rh * 2 + 1],
                                 acc[2][mt][nt][rh * 2 + 1], bi1, bf1, bg1, cv.y);
                *(float2*)(out + idx) = ov;
            }
        }
    }
}

extern "C" void kernel_launch(void* const* d_in, const int* in_sizes, int n_in,
                              void* d_out, int out_size) {
    const float* x   = (const float*)d_in[0];
    const float* h   = (const float*)d_in[1];
    const float* c   = (const float*)d_in[2];
    const float* Wii = (const float*)d_in[3];
    const float* bii = (const float*)d_in[4];
    const float* Whi = (const float*)d_in[5];
    const float* bhi = (const float*)d_in[6];
    const float* Wif = (const float*)d_in[7];
    const float* bif = (const float*)d_in[8];
    const float* Whf = (const float*)d_in[9];
    const float* bhf = (const float*)d_in[10];
    const float* Wig = (const float*)d_in[11];
    const float* big = (const float*)d_in[12];
    const float* Whg = (const float*)d_in[13];
    const float* bhg = (const float*)d_in[14];
    float* out = (float*)d_out;

    cudaFuncSetAttribute(lstm_mma_kernel,
                         cudaFuncAttributeMaxDynamicSharedMemorySize, SMEM_BYTES);

    prep_x_kernel<<<(long)BATCH * KTOT / 4 / 256, 256>>>(x, h);
    prep_w_kernel<<<(long)GATES * HID * KTOT / 4 / 256, 256>>>(
        Wii, Whi, Wif, Whf, Wig, Whg);

    dim3 grid((BATCH / BM) * (HID / BN_G));
    lstm_mma_kernel<<<grid, 256, SMEM_BYTES>>>(
        c, bii, bhi, bif, bhf, big, bhg, out);
}

// round 4
// speedup vs baseline: 1.2088x; 1.0291x over previous
#include <cuda_runtime.h>
#include <cstdint>

// ---------------------------------------------------------------------------
// LSTM cell, sm_103 base target. R4: 512 threads / 16 warps per CTA (4x4 warp
// grid) to double per-SMSP latency hiding; tf32 rounding in prepass kernels;
// cp.async 4-stage pipeline -> ldmatrix -> mma.sync tf32 -> fused epilogue.
// ---------------------------------------------------------------------------

static constexpr int BATCH = 16384;
static constexpr int HID   = 1024;
static constexpr int KTOT  = 2048;
static constexpr int BM    = 128;
static constexpr int BN_G  = 64;
static constexpr int GATES = 3;
static constexpr int BK    = 32;
static constexpr int KSTEPS = KTOT / BK;   // 64
static constexpr int NSTAGE = 4;
static constexpr int NTHR   = 512;

static constexpr uint32_t A_ST  = BM * 128;            // 16 KB
static constexpr uint32_t B_ST  = GATES * BN_G * 128;  // 24 KB
static constexpr uint32_t STAGE = A_ST + B_ST;         // 40 KB
static constexpr uint32_t SMEM_BYTES = NSTAGE * STAGE + 1024;

__device__ float g_X[(long)BATCH * KTOT];          // 134 MB tf32-rounded [x|h]
__device__ float g_W[(long)GATES * HID * KTOT];    // 25 MB tf32-rounded gate-concat W

__device__ __forceinline__ uint32_t smem_u32(const void* p) {
    uint32_t a;
    asm("{ .reg .u64 t; cvta.to.shared.u64 t, %1; cvt.u32.u64 %0, t; }"
        : "=r"(a) : "l"(p));
    return a;
}

#define CP_ASYNC16(dst, src) \
    asm volatile("cp.async.cg.shared.global [%0], [%1], 16;" :: "r"(dst), "l"(src) : "memory")
#define CP_COMMIT() asm volatile("cp.async.commit_group;" ::: "memory")

#define LDSM4(r, addr)                                                         \
    asm volatile("ldmatrix.sync.aligned.m8n8.x4.shared.b16 {%0,%1,%2,%3}, [%4];" \
        : "=r"((r)[0]), "=r"((r)[1]), "=r"((r)[2]), "=r"((r)[3]) : "r"(addr))

#define MMA_TF32(d, a, b0, b1)                                                 \
    asm volatile("mma.sync.aligned.m16n8k8.row.col.f32.tf32.tf32.f32 "         \
        "{%0,%1,%2,%3},{%4,%5,%6,%7},{%8,%9},{%0,%1,%2,%3};"                   \
        : "+f"((d)[0]), "+f"((d)[1]), "+f"((d)[2]), "+f"((d)[3])               \
        : "r"((a)[0]), "r"((a)[1]), "r"((a)[2]), "r"((a)[3]), "r"(b0), "r"(b1))

__device__ __forceinline__ float f2tf_f(float v) {
    uint32_t o;
    asm("cvt.rna.tf32.f32 %0, %1;" : "=r"(o) : "r"(__float_as_uint(v)));
    return __uint_as_float(o);
}

__device__ __forceinline__ float4 round4(float4 v) {
    v.x = f2tf_f(v.x); v.y = f2tf_f(v.y); v.z = f2tf_f(v.z); v.w = f2tf_f(v.w);
    return v;
}

// ---- prepass ---------------------------------------------------------------
__global__ __launch_bounds__(256)
void prep_x_kernel(const float* __restrict__ x, const float* __restrict__ h) {
    const long i = (long)blockIdx.x * 256 + threadIdx.x;
    const long row = i >> 9;
    const int  c4  = (int)(i & 511);
    float4 v = (c4 < 256) ? ((const float4*)x)[row * 256 + c4]
                          : ((const float4*)h)[row * 256 + (c4 - 256)];
    ((float4*)g_X)[i] = round4(v);
}

__global__ __launch_bounds__(256)
void prep_w_kernel(const float* __restrict__ Wii, const float* __restrict__ Whi,
                   const float* __restrict__ Wif, const float* __restrict__ Whf,
                   const float* __restrict__ Wig, const float* __restrict__ Whg) {
    const long i = (long)blockIdx.x * 256 + threadIdx.x;
    const long grow = i >> 9;
    const int  c4   = (int)(i & 511);
    const int  g    = (int)(grow >> 10);
    const long r    = grow & 1023;
    const float* Wx = (g == 0) ? Wii : (g == 1) ? Wif : Wig;
    const float* Wh = (g == 0) ? Whi : (g == 1) ? Whf : Whg;
    float4 v = (c4 < 256) ? ((const float4*)Wx)[r * 256 + c4]
                          : ((const float4*)Wh)[r * 256 + (c4 - 256)];
    ((float4*)g_W)[i] = round4(v);
}

__device__ __forceinline__ float lstm_elem(float gi, float gf, float gg,
                                           float bi, float bf, float bg, float cv) {
    float vi = gi + bi;
    float vf = gf + bf;
    float vg = gg + bg;
    float si = 1.0f / (1.0f + __expf(-vi));
    float sf = 1.0f / (1.0f + __expf(-vf));
    float vgc = fminf(15.0f, fmaxf(-15.0f, vg));
    float e2  = __expf(2.0f * vgc);
    float tg  = (e2 - 1.0f) / (e2 + 1.0f);
    return fmaf(sf, cv, si * tg);
}

__global__ __launch_bounds__(NTHR, 1)
void lstm_mma_kernel(const float* __restrict__ c,
                     const float* __restrict__ bii, const float* __restrict__ bhi,
                     const float* __restrict__ bif, const float* __restrict__ bhf,
                     const float* __restrict__ big, const float* __restrict__ bhg,
                     float* __restrict__ out) {
    extern __shared__ char smem_raw[];
    const uint32_t raw   = smem_u32(smem_raw);
    const uint32_t tiles = (raw + 1023u) & ~1023u;
    float* bias = (float*)(smem_raw + (tiles - raw) + NSTAGE * STAGE);

    const int tid  = threadIdx.x;
    const int lane = tid & 31;
    const int wid  = tid >> 5;
    const int wm   = wid >> 2;      // 0..3  (32 rows)
    const int wn   = wid & 3;       // 0..3  (16 cols per gate)

    const int m0 = (int)(blockIdx.x >> 4) * BM;
    const int n0 = (int)(blockIdx.x & 15) * BN_G;

    if (tid < 192) {
        const int g = tid >> 6, j = tid & 63, n = n0 + j;
        float v;
        if (g == 0)      v = bii[n] + bhi[n];
        else if (g == 1) v = bif[n] + bhf[n];
        else             v = big[n] + bhg[n];
        bias[tid] = v;
    }

    // producer invariants (512 threads) -------------------------------------
    uint32_t aoffs[2]; const float* asrc[2];
    #pragma unroll
    for (int i = 0; i < 2; ++i) {
        const int id = tid + i * NTHR;
        const int row = id >> 3, ch = id & 7;
        aoffs[i] = (uint32_t)(row * 128 + ((ch ^ (row & 7)) << 4));
        asrc[i]  = g_X + (long)(m0 + row) * KTOT + ch * 4;
    }
    uint32_t boffs[3]; const float* bsrc[3];
    #pragma unroll
    for (int i = 0; i < 3; ++i) {
        const int id = tid + i * NTHR;
        const int grow = id >> 3, ch = id & 7;
        const int g = grow >> 6, r = grow & 63;
        boffs[i] = (uint32_t)(grow * 128 + ((ch ^ (r & 7)) << 4));
        bsrc[i]  = g_W + (long)(g * HID + n0 + r) * KTOT + ch * 4;
    }

    // consumer invariants ----------------------------------------------------
    const uint32_t s7 = (uint32_t)(lane & 7);
    const int lmrow = (lane & 7) + ((lane >> 3) & 1) * 8;
    const int lkh   = lane >> 4;
    uint32_t arow[2], brow[3];
    #pragma unroll
    for (int mt = 0; mt < 2; ++mt)
        arow[mt] = (uint32_t)((wm * 32 + mt * 16 + lmrow) * 128);
    #pragma unroll
    for (int g = 0; g < GATES; ++g)
        brow[g] = (uint32_t)((g * 64 + wn * 16 + lmrow) * 128);

    float acc[GATES][2][2][4];
    #pragma unroll
    for (int g = 0; g < GATES; ++g)
        #pragma unroll
        for (int mt = 0; mt < 2; ++mt)
            #pragma unroll
            for (int nt = 0; nt < 2; ++nt)
                #pragma unroll
                for (int q = 0; q < 4; ++q) acc[g][mt][nt][q] = 0.0f;

    auto load_stage = [&](int s, int ks) {
        const int kk = ks * BK;
        const uint32_t sAs = tiles + (uint32_t)s * STAGE;
        const uint32_t sBs = sAs + A_ST;
        #pragma unroll
        for (int i = 0; i < 2; ++i)
            CP_ASYNC16(sAs + aoffs[i], asrc[i] + kk);
        #pragma unroll
        for (int i = 0; i < 3; ++i)
            CP_ASYNC16(sBs + boffs[i], bsrc[i] + kk);
    };

    #pragma unroll
    for (int s = 0; s < NSTAGE - 1; ++s) { load_stage(s, s); CP_COMMIT(); }

    for (int ks = 0; ks < KSTEPS; ++ks) {
        asm volatile("cp.async.wait_group %0;" :: "n"(NSTAGE - 2));
        __syncthreads();

        const uint32_t sAs = tiles + (uint32_t)(ks & (NSTAGE - 1)) * STAGE;
        const uint32_t sBs = sAs + A_ST;

        #pragma unroll
        for (int kst = 0; kst < 4; ++kst) {
            const uint32_t off = (uint32_t)(((kst * 2 + lkh) ^ s7) << 4);
            uint32_t a[2][4], b[GATES][4];
            #pragma unroll
            for (int mt = 0; mt < 2; ++mt) LDSM4(a[mt], sAs + arow[mt] + off);
            #pragma unroll
            for (int g = 0; g < GATES; ++g) LDSM4(b[g], sBs + brow[g] + off);
            #pragma unroll
            for (int g = 0; g < GATES; ++g)
                #pragma unroll
                for (int mt = 0; mt < 2; ++mt) {
                    MMA_TF32(acc[g][mt][0], a[mt], b[g][0], b[g][2]);
                    MMA_TF32(acc[g][mt][1], a[mt], b[g][1], b[g][3]);
                }
        }

        const int pf = ks + NSTAGE - 1;
        if (pf < KSTEPS) load_stage(pf & (NSTAGE - 1), pf);
        CP_COMMIT();
    }

    // epilogue ---------------------------------------------------------------
    #pragma unroll
    for (int mt = 0; mt < 2; ++mt) {
        const int mrow = m0 + wm * 32 + mt * 16 + (lane >> 2);
        #pragma unroll
        for (int nt = 0; nt < 2; ++nt) {
            const int nl = wn * 16 + nt * 8 + (lane & 3) * 2;
            const float bi0 = bias[nl],       bi1 = bias[nl + 1];
            const float bf0 = bias[64 + nl],  bf1 = bias[64 + nl + 1];
            const float bg0 = bias[128 + nl], bg1 = bias[128 + nl + 1];
            #pragma unroll
            for (int rh = 0; rh < 2; ++rh) {
                const long idx = (long)(mrow + rh * 8) * HID + n0 + nl;
                const float2 cv = *(const float2*)(c + idx);
                float2 ov;
                ov.x = lstm_elem(acc[0][mt][nt][rh * 2],
                                 acc[1][mt][nt][rh * 2],
                                 acc[2][mt][nt][rh * 2], bi0, bf0, bg0, cv.x);
                ov.y = lstm_elem(acc[0][mt][nt][rh * 2 + 1],
                                 acc[1][mt][nt][rh * 2 + 1],
                                 acc[2][mt][nt][rh * 2 + 1], bi1, bf1, bg1, cv.y);
                *(float2*)(out + idx) = ov;
            }
        }
    }
}

extern "C" void kernel_launch(void* const* d_in, const int* in_sizes, int n_in,
                              void* d_out, int out_size) {
    const float* x   = (const float*)d_in[0];
    const float* h   = (const float*)d_in[1];
    const float* c   = (const float*)d_in[2];
    const float* Wii = (const float*)d_in[3];
    const float* bii = (const float*)d_in[4];
    const float* Whi = (const float*)d_in[5];
    const float* bhi = (const float*)d_in[6];
    const float* Wif = (const float*)d_in[7];
    const float* bif = (const float*)d_in[8];
    const float* Whf = (const float*)d_in[9];
    const float* bhf = (const float*)d_in[10];
    const float* Wig = (const float*)d_in[11];
    const float* big = (const float*)d_in[12];
    const float* Whg = (const float*)d_in[13];
    const float* bhg = (const float*)d_in[14];
    float* out = (float*)d_out;

    cudaFuncSetAttribute(lstm_mma_kernel,
                         cudaFuncAttributeMaxDynamicSharedMemorySize, SMEM_BYTES);

    prep_x_kernel<<<(long)BATCH * KTOT / 4 / 256, 256>>>(x, h);
    prep_w_kernel<<<(long)GATES * HID * KTOT / 4 / 256, 256>>>(
        Wii, Whi, Wif, Whf, Wig, Whg);

    dim3 grid((BATCH / BM) * (HID / BN_G));
    lstm_mma_kernel<<<grid, NTHR, SMEM_BYTES>>>(
        c, bii, bhi, bif, bhf, big, bhg, out);
}